// round 1
// baseline (speedup 1.0000x reference)
#include <cuda_runtime.h>

#define NB 16
#define HW 1024
#define CI 512
#define CA 512
#define KL 256
#define NH 8
#define HD 64

// Scratch (alloc-free: __device__ globals)
__device__ float g_q[NB * HW * CA];      // 32 MB
__device__ float g_k[NB * KL * CA];      //  8 MB
__device__ float g_v[NB * KL * CA];      //  8 MB
__device__ float g_attn[NB * HW * CA];   // 32 MB
__device__ float g_y[NB * HW * CI];      // 32 MB

__device__ __forceinline__ unsigned long long ffma2(unsigned long long a,
                                                    unsigned long long b,
                                                    unsigned long long c) {
    unsigned long long d;
    asm("fma.rn.f32x2 %0, %1, %2, %3;" : "=l"(d) : "l"(a), "l"(b), "l"(c));
    return d;
}
__device__ __forceinline__ unsigned long long pack2(float x, float y) {
    unsigned long long d;
    asm("mov.b64 %0, {%1, %2};" : "=l"(d) : "f"(x), "f"(y));
    return d;
}
__device__ __forceinline__ float2 unpack2(unsigned long long a) {
    float2 f;
    asm("mov.b64 {%0, %1}, %2;" : "=f"(f.x), "=f"(f.y) : "l"(a));
    return f;
}

// ---------------------------------------------------------------------------
// GEMM: C[M,512] = A[M,512] @ B[512,512] + bias
// MODE 0: Q  (A = img_feat, transposed access A[m][k] = img[b, k, s]) -> g_q
// MODE 1: K  (A = audio, row-major) -> g_k
// MODE 2: V  (A = audio, row-major) -> g_v
// MODE 3: O  (A = g_attn, row-major) -> g_y
// 128x128 tile, BK=8, 256 threads, 8x8 per thread, all math in fma.rn.f32x2.
// ---------------------------------------------------------------------------
template <int MODE>
__global__ void __launch_bounds__(256, 2)
gemm_bias(const float* __restrict__ A, const float* __restrict__ Bm,
          const float* __restrict__ bias) {
    __shared__ float As[8 * 128];
    __shared__ float Bs[8 * 128];
    const int t = threadIdx.x;
    const int bx = blockIdx.x;   // n tile (0..3)
    const int by = blockIdx.y;   // m tile
    const int tx = t & 15, ty = t >> 4;

    float* C = (MODE == 0) ? g_q : (MODE == 1) ? g_k : (MODE == 2) ? g_v : g_y;

    const float* Ap;
    if (MODE == 0) {
        const int bimg = (by * 128) >> 10;
        const int s0 = (by * 128) & 1023;
        Ap = A + (size_t)bimg * (CI * HW) + s0;     // + k*1024 + m
    } else if (MODE == 3) {
        Ap = g_attn + (size_t)(by * 128) * 512;
    } else {
        Ap = A + (size_t)(by * 128) * 512;
    }
    const float* Bp = Bm + bx * 128;

    unsigned long long c2[4][8];
#pragma unroll
    for (int p = 0; p < 4; p++)
#pragma unroll
        for (int j = 0; j < 8; j++) c2[p][j] = 0ULL;

#pragma unroll 1
    for (int kt = 0; kt < 64; kt++) {
        const int k0 = kt * 8;
        if (MODE == 0) {
            const int kk = t >> 5, mo = (t & 31) << 2;
            *(float4*)&As[kk * 128 + mo] =
                *(const float4*)&Ap[(size_t)(k0 + kk) * 1024 + mo];
        } else {
            const int row = t >> 1, qd = (t & 1) << 2;
            float4 av = *(const float4*)&Ap[(size_t)row * 512 + k0 + qd];
            As[(qd + 0) * 128 + row] = av.x;
            As[(qd + 1) * 128 + row] = av.y;
            As[(qd + 2) * 128 + row] = av.z;
            As[(qd + 3) * 128 + row] = av.w;
        }
        {
            const int kk = t >> 5, no = (t & 31) << 2;
            *(float4*)&Bs[kk * 128 + no] =
                *(const float4*)&Bp[(size_t)(k0 + kk) * 512 + no];
        }
        __syncthreads();
#pragma unroll
        for (int kk = 0; kk < 8; kk++) {
            unsigned long long a2[4];
            a2[0] = *(const unsigned long long*)&As[kk * 128 + ty * 4];
            a2[1] = *(const unsigned long long*)&As[kk * 128 + ty * 4 + 2];
            a2[2] = *(const unsigned long long*)&As[kk * 128 + 64 + ty * 4];
            a2[3] = *(const unsigned long long*)&As[kk * 128 + 64 + ty * 4 + 2];
            const float4 b0 = *(const float4*)&Bs[kk * 128 + tx * 4];
            const float4 b1 = *(const float4*)&Bs[kk * 128 + 64 + tx * 4];
            unsigned long long bd[8];
            bd[0] = pack2(b0.x, b0.x); bd[1] = pack2(b0.y, b0.y);
            bd[2] = pack2(b0.z, b0.z); bd[3] = pack2(b0.w, b0.w);
            bd[4] = pack2(b1.x, b1.x); bd[5] = pack2(b1.y, b1.y);
            bd[6] = pack2(b1.z, b1.z); bd[7] = pack2(b1.w, b1.w);
#pragma unroll
            for (int p = 0; p < 4; p++)
#pragma unroll
                for (int j = 0; j < 8; j++)
                    c2[p][j] = ffma2(a2[p], bd[j], c2[p][j]);
        }
        __syncthreads();
    }

    const float4 bv0 = *(const float4*)&bias[bx * 128 + tx * 4];
    const float4 bv1 = *(const float4*)&bias[bx * 128 + 64 + tx * 4];
#pragma unroll
    for (int p = 0; p < 4; p++) {
        const int r0 = (p < 2) ? (ty * 4 + 2 * p) : (64 + ty * 4 + 2 * p - 4);
        float2 cf[8];
#pragma unroll
        for (int j = 0; j < 8; j++) cf[j] = unpack2(c2[p][j]);
#pragma unroll
        for (int half = 0; half < 2; half++) {
            const size_t m = (size_t)(by * 128 + r0 + half);
            float4 o0, o1;
            o0.x = (half ? cf[0].y : cf[0].x) + bv0.x;
            o0.y = (half ? cf[1].y : cf[1].x) + bv0.y;
            o0.z = (half ? cf[2].y : cf[2].x) + bv0.z;
            o0.w = (half ? cf[3].y : cf[3].x) + bv0.w;
            o1.x = (half ? cf[4].y : cf[4].x) + bv1.x;
            o1.y = (half ? cf[5].y : cf[5].x) + bv1.y;
            o1.z = (half ? cf[6].y : cf[6].x) + bv1.z;
            o1.w = (half ? cf[7].y : cf[7].x) + bv1.w;
            *(float4*)&C[m * 512 + bx * 128 + tx * 4] = o0;
            *(float4*)&C[m * 512 + bx * 128 + 64 + tx * 4] = o1;
        }
    }
}

// ---------------------------------------------------------------------------
// Attention: per block = (b, h, 64-query tile). K_LEN=256 fits one tile.
// smem: Qs^T[64d][65], Ks^T[64d][257], Vs[256k][64d]; weights reuse Ks region.
// Each warp owns 8 query rows; lane owns k = lane + 32j (scores) / d = lane,
// lane+32 (AV). All accumulation in fma.rn.f32x2.
// ---------------------------------------------------------------------------
#define ATTN_SMEM_FLOATS (64 * 65 + 64 * 257 + 256 * 64)
#define ATTN_SMEM_BYTES (ATTN_SMEM_FLOATS * 4)

__global__ void __launch_bounds__(256, 1) attn_kernel() {
    extern __shared__ float sm[];
    float* Qs = sm;                    // 64*65
    float* Ks = sm + 64 * 65;          // 64*257
    float* Vs = Ks + 64 * 257;         // 256*64
    float* Ws = Ks;                    // alias after score phase

    const int bh = blockIdx.x;
    const int b = bh >> 3, h = bh & 7;
    const int q0 = blockIdx.y << 6;
    const int t = threadIdx.x;

    const float* qb = g_q + (size_t)b * (HW * CA) + (size_t)q0 * CA + h * HD;
    const float* kb = g_k + (size_t)b * (KL * CA) + h * HD;
    const float* vb = g_v + (size_t)b * (KL * CA) + h * HD;

#pragma unroll
    for (int r = 0; r < 16; r++) {       // Q tile, transposed store
        const int e = t + 256 * r;
        const int qq = e >> 6, d = e & 63;
        Qs[d * 65 + qq] = qb[(size_t)qq * CA + d];
    }
#pragma unroll 8
    for (int r = 0; r < 64; r++) {       // K tile, transposed store
        const int e = t + 256 * r;
        const int kk = e >> 6, d = e & 63;
        Ks[d * 257 + kk] = kb[(size_t)kk * CA + d];
    }
#pragma unroll
    for (int r = 0; r < 16; r++) {       // V tile, direct
        const int u = t + 256 * r;
        const int kk = u >> 4, d4 = (u & 15) << 2;
        *(float4*)&Vs[kk * 64 + d4] = *(const float4*)&vb[(size_t)kk * CA + d4];
    }
    __syncthreads();

    const int warp = t >> 5, lane = t & 31;

    // --- scores: S[8q][8k per lane] = Q @ K^T ---
    unsigned long long s2[8][4];
#pragma unroll
    for (int i = 0; i < 8; i++)
#pragma unroll
        for (int j = 0; j < 4; j++) s2[i][j] = 0ULL;

#pragma unroll 1
    for (int kk = 0; kk < 64; kk++) {
        const float* kr = Ks + kk * 257 + lane;
        const float* qr = Qs + kk * 65 + warp * 8;
        unsigned long long b2[4];
#pragma unroll
        for (int j = 0; j < 4; j++) b2[j] = pack2(kr[64 * j], kr[64 * j + 32]);
#pragma unroll
        for (int i = 0; i < 8; i++) {
            const float a = qr[i];
            const unsigned long long ad = pack2(a, a);
#pragma unroll
            for (int j = 0; j < 4; j++) s2[i][j] = ffma2(ad, b2[j], s2[i][j]);
        }
    }
    __syncthreads();   // all warps done reading Ks (Ws aliases it)

    // --- softmax (scale = HEAD_DIM^-0.5 = 0.125) ---
#pragma unroll
    for (int i = 0; i < 8; i++) {
        float2 e[4];
        float m = -1e30f;
#pragma unroll
        for (int j = 0; j < 4; j++) {
            e[j] = unpack2(s2[i][j]);
            m = fmaxf(m, fmaxf(e[j].x, e[j].y));
        }
#pragma unroll
        for (int off = 16; off > 0; off >>= 1)
            m = fmaxf(m, __shfl_xor_sync(0xffffffffu, m, off));
        float sum = 0.f;
#pragma unroll
        for (int j = 0; j < 4; j++) {
            e[j].x = __expf(0.125f * (e[j].x - m));
            e[j].y = __expf(0.125f * (e[j].y - m));
            sum += e[j].x + e[j].y;
        }
#pragma unroll
        for (int off = 16; off > 0; off >>= 1)
            sum += __shfl_xor_sync(0xffffffffu, sum, off);
        const float inv = __frcp_rn(sum);
        float* wrow = Ws + (size_t)(warp * 8 + i) * 256 + lane;
#pragma unroll
        for (int j = 0; j < 4; j++) {
            wrow[64 * j] = e[j].x * inv;
            wrow[64 * j + 32] = e[j].y * inv;
        }
    }
    __syncthreads();

    // --- AV: O[8q][2d per lane] = W @ V ---
    unsigned long long o2[8];
#pragma unroll
    for (int i = 0; i < 8; i++) o2[i] = 0ULL;
#pragma unroll 2
    for (int k = 0; k < 256; k++) {
        const unsigned long long v2 = pack2(Vs[k * 64 + lane], Vs[k * 64 + lane + 32]);
        const float* wr = Ws + (size_t)(warp * 8) * 256 + k;
#pragma unroll
        for (int i = 0; i < 8; i++) {
            const float w = wr[i * 256];
            o2[i] = ffma2(pack2(w, w), v2, o2[i]);
        }
    }
    float* ob = g_attn + (size_t)b * (HW * CA) + (size_t)(q0 + warp * 8) * CA + h * HD;
#pragma unroll
    for (int i = 0; i < 8; i++) {
        const float2 f = unpack2(o2[i]);
        ob[(size_t)i * CA + lane] = f.x;
        ob[(size_t)i * CA + lane + 32] = f.y;
    }
}

// ---------------------------------------------------------------------------
// Residual + LayerNorm + transpose to [b, c, h, w].
// Block = (b, 32 s-rows). Tile staged in smem with pitch 513 (conflict-free
// both row-wise and column-wise). Coalesced reads of g_y AND coalesced
// transposed writes of out.
// ---------------------------------------------------------------------------
#define LN_SMEM_BYTES (32 * 513 * 4)

__global__ void __launch_bounds__(256, 1)
ln_kernel(const float* __restrict__ img, const float* __restrict__ gamma,
          const float* __restrict__ beta, float* __restrict__ out) {
    extern __shared__ float sm[];   // [32][513]
    __shared__ float smu[32], srv[32];
    const int b = blockIdx.x >> 5;
    const int s0 = (blockIdx.x & 31) << 5;
    const int t = threadIdx.x;

#pragma unroll
    for (int r = 0; r < 16; r++) {     // load y = proj + bias
        const int u = t + 256 * r;
        const int s = u >> 7, c4 = (u & 127) << 2;
        const float4 v = *(const float4*)&g_y[((size_t)(b * HW + s0 + s)) * CI + c4];
        float* dst = sm + s * 513 + c4;
        dst[0] = v.x; dst[1] = v.y; dst[2] = v.z; dst[3] = v.w;
    }
    __syncthreads();
#pragma unroll 8
    for (int r = 0; r < 64; r++) {     // add residual img_seq (coalesced in s)
        const int u = t + 256 * r;
        const int c = u >> 5, s = u & 31;
        sm[s * 513 + c] += img[(size_t)b * (CI * HW) + (size_t)c * HW + s0 + s];
    }
    __syncthreads();

    const int warp = t >> 5, lane = t & 31;
#pragma unroll
    for (int rr = 0; rr < 4; rr++) {
        const int s = warp * 4 + rr;
        const float* row = sm + s * 513;
        float sum = 0.f;
#pragma unroll
        for (int i = 0; i < 16; i++) sum += row[lane + 32 * i];
#pragma unroll
        for (int off = 16; off > 0; off >>= 1)
            sum += __shfl_xor_sync(0xffffffffu, sum, off);
        const float mu = sum * (1.0f / 512.0f);
        float var = 0.f;
#pragma unroll
        for (int i = 0; i < 16; i++) {
            const float d = row[lane + 32 * i] - mu;
            var += d * d;
        }
#pragma unroll
        for (int off = 16; off > 0; off >>= 1)
            var += __shfl_xor_sync(0xffffffffu, var, off);
        var *= (1.0f / 512.0f);
        if (lane == 0) { smu[s] = mu; srv[s] = rsqrtf(var + 1e-5f); }
    }
    __syncthreads();

    const float mu = smu[lane], rv = srv[lane];
#pragma unroll 4
    for (int ci = 0; ci < 64; ci++) {
        const int c = warp * 64 + ci;
        const float val = (sm[lane * 513 + c] - mu) * rv * gamma[c] + beta[c];
        out[(size_t)b * (CI * HW) + (size_t)c * HW + s0 + lane] = val;
    }
}

// ---------------------------------------------------------------------------
extern "C" void kernel_launch(void* const* d_in, const int* in_sizes, int n_in,
                              void* d_out, int out_size) {
    (void)in_sizes; (void)n_in; (void)out_size;
    const float* img   = (const float*)d_in[0];
    const float* aud   = (const float*)d_in[1];
    const float* Wq    = (const float*)d_in[2];
    const float* bq    = (const float*)d_in[3];
    const float* Wk    = (const float*)d_in[4];
    const float* bk    = (const float*)d_in[5];
    const float* Wv    = (const float*)d_in[6];
    const float* bv    = (const float*)d_in[7];
    const float* Wo    = (const float*)d_in[8];
    const float* bo    = (const float*)d_in[9];
    const float* gamma = (const float*)d_in[10];
    const float* beta  = (const float*)d_in[11];
    float* out = (float*)d_out;

    cudaFuncSetAttribute((const void*)attn_kernel,
                         cudaFuncAttributeMaxDynamicSharedMemorySize,
                         ATTN_SMEM_BYTES);
    cudaFuncSetAttribute((const void*)ln_kernel,
                         cudaFuncAttributeMaxDynamicSharedMemorySize,
                         LN_SMEM_BYTES);

    gemm_bias<0><<<dim3(4, 128), 256>>>(img, Wq, bq);   // Q  = img_seq @ Wq + bq
    gemm_bias<1><<<dim3(4, 32), 256>>>(aud, Wk, bk);    // K  = audio @ Wk + bk
    gemm_bias<2><<<dim3(4, 32), 256>>>(aud, Wv, bv);    // V  = audio @ Wv + bv
    attn_kernel<<<dim3(128, 16), 256, ATTN_SMEM_BYTES>>>();
    gemm_bias<3><<<dim3(4, 128), 256>>>(nullptr, Wo, bo); // proj = attn @ Wo + bo
    ln_kernel<<<512, 256, LN_SMEM_BYTES>>>(img, gamma, beta, out);
}

// round 4
// speedup vs baseline: 1.9106x; 1.9106x over previous
#include <cuda_runtime.h>
#include <cstdint>

#define NB 16
#define HW 1024
#define CI 512
#define CA 512
#define KL 256
#define HD 64

// Scratch (alloc-free: __device__ globals)
__device__ float g_q[NB * HW * CA];
__device__ float g_k[NB * KL * CA];
__device__ float g_v[NB * KL * CA];
__device__ float g_attn[NB * HW * CA];   // tf32-rounded by attn epilogue
__device__ float g_y[NB * HW * CI];
__device__ float g_imgr[NB * CI * HW];   // tf32-rounded img
__device__ float g_audr[NB * KL * CA];   // tf32-rounded audio
__device__ float g_wr[4 * 512 * 512];    // tf32-rounded weights (orig [K][N] layout)

// ---------------------------------------------------------------------------
// Helpers
// ---------------------------------------------------------------------------
__device__ __forceinline__ uint32_t smem_u32(const void* p) {
    uint32_t a;
    asm("{ .reg .u64 t; cvta.to.shared.u64 t, %1; cvt.u32.u64 %0, t; }"
        : "=r"(a) : "l"(p));
    return a;
}
__device__ __forceinline__ float cvt_tf32(float x) {
    uint32_t r;
    asm("cvt.rna.tf32.f32 %0, %1;" : "=r"(r) : "f"(x));
    return __uint_as_float(r);
}
#define CP_ASYNC16(dst, src) \
    asm volatile("cp.async.cg.shared.global [%0], [%1], 16;" \
                 :: "r"(dst), "l"(src) : "memory")
#define CP_COMMIT() asm volatile("cp.async.commit_group;" ::: "memory")
#define CP_WAIT(n)  asm volatile("cp.async.wait_group %0;" :: "n"(n) : "memory")

__device__ __forceinline__ void mma_tf32(float (&c)[4], const uint32_t (&a)[4],
                                         const uint32_t (&b)[2]) {
    asm volatile(
        "mma.sync.aligned.m16n8k8.row.col.f32.tf32.tf32.f32 "
        "{%0,%1,%2,%3}, {%4,%5,%6,%7}, {%8,%9}, {%0,%1,%2,%3};"
        : "+f"(c[0]), "+f"(c[1]), "+f"(c[2]), "+f"(c[3])
        : "r"(a[0]), "r"(a[1]), "r"(a[2]), "r"(a[3]), "r"(b[0]), "r"(b[1]));
}

// f32x2 helpers (fp32 attention math)
__device__ __forceinline__ unsigned long long ffma2(unsigned long long a,
                                                    unsigned long long b,
                                                    unsigned long long c) {
    unsigned long long d;
    asm("fma.rn.f32x2 %0, %1, %2, %3;" : "=l"(d) : "l"(a), "l"(b), "l"(c));
    return d;
}
__device__ __forceinline__ unsigned long long pack2(float x, float y) {
    unsigned long long d;
    asm("mov.b64 %0, {%1, %2};" : "=l"(d) : "f"(x), "f"(y));
    return d;
}
__device__ __forceinline__ float2 unpack2(unsigned long long a) {
    float2 f;
    asm("mov.b64 {%0, %1}, %2;" : "=f"(f.x), "=f"(f.y) : "l"(a));
    return f;
}

// ---------------------------------------------------------------------------
// tf32 pre-rounding (unbiased rna — truncation would bias results by ~1e-3)
// ---------------------------------------------------------------------------
__global__ void round_tf32(const float4* __restrict__ src,
                           float4* __restrict__ dst, int n4) {
    const int i = blockIdx.x * blockDim.x + threadIdx.x;
    if (i < n4) {
        float4 v = src[i];
        v.x = cvt_tf32(v.x); v.y = cvt_tf32(v.y);
        v.z = cvt_tf32(v.z); v.w = cvt_tf32(v.w);
        dst[i] = v;
    }
}

// ---------------------------------------------------------------------------
// tf32 mma.sync GEMM: C[M,512] = A[M,512] @ W[512,512] + bias
// 128x128 tile, BK=32, 256 threads (8 warps, 2m x 4n), warp tile 64x32.
// cp.async double-buffered. smem layouts:
//   A k-major (MODE 0: img [k][m])      -> As[k][136]   (bank = 8*tg+g, clean)
//   A m-major (MODE 1/2/3: row-major)   -> As[m][36]    (bank = 4*g+tg, clean)
//   B (weights, original [K][N] layout) -> Bs[k][136]
// ---------------------------------------------------------------------------
#define A_K_PAD 136
#define A_M_PAD 36
#define B_PAD 136
#define B_OFF 4608                  // floats (max A area: 128*36)
#define STAGE_F 8960                // B_OFF + 32*136
#define GT_SMEM_BYTES (2 * STAGE_F * 4)

template <int MODE>
__device__ __forceinline__ void gt_issue(uint32_t sb, int stage, int kc,
                                         const float* __restrict__ Ap,
                                         const float* __restrict__ Wp, int t) {
    const int k0 = kc * 32;
    const uint32_t abase = sb + (uint32_t)(stage * STAGE_F) * 4;
    const uint32_t bbase = abase + B_OFF * 4;
#pragma unroll
    for (int r = 0; r < 4; r++) {
        const int idx = t + 256 * r;
        if (MODE == 0) {
            const int k = idx >> 5, m4 = (idx & 31) << 2;
            CP_ASYNC16(abase + (uint32_t)(k * A_K_PAD + m4) * 4,
                       Ap + (size_t)(k0 + k) * HW + m4);
        } else {
            const int m = idx >> 3, k4 = (idx & 7) << 2;
            CP_ASYNC16(abase + (uint32_t)(m * A_M_PAD + k4) * 4,
                       Ap + (size_t)m * 512 + k0 + k4);
        }
    }
#pragma unroll
    for (int r = 0; r < 4; r++) {
        const int idx = t + 256 * r;
        const int k = idx >> 5, n4 = (idx & 31) << 2;
        CP_ASYNC16(bbase + (uint32_t)(k * B_PAD + n4) * 4,
                   Wp + (size_t)(k0 + k) * 512 + n4);
    }
    CP_COMMIT();
}

template <int MODE>
__global__ void __launch_bounds__(256)
gemm_tc(const float* __restrict__ A, const float* __restrict__ W,
        const float* __restrict__ bias) {
    extern __shared__ float sm[];
    const uint32_t sb = smem_u32(sm);
    const int t = threadIdx.x, warp = t >> 5, lane = t & 31;
    const int g = lane >> 2, tg = lane & 3;
    const int wm = (warp >> 2) * 64, wn = (warp & 3) * 32;
    const int bx = blockIdx.x, by = blockIdx.y;

    float* C = (MODE == 0) ? g_q : (MODE == 1) ? g_k : (MODE == 2) ? g_v : g_y;
    const float* Ap;
    int rowbase;
    if (MODE == 0) {
        Ap = A + (size_t)(by >> 3) * (CI * HW) + ((by & 7) << 7);
        rowbase = (by >> 3) * HW + ((by & 7) << 7);
    } else if (MODE == 3) {
        Ap = g_attn + (size_t)by * 128 * 512;
        rowbase = by * 128;
    } else {
        Ap = A + (size_t)by * 128 * 512;
        rowbase = by * 128;
    }
    const float* Wp = W + bx * 128;

    float acc[4][4][4];
#pragma unroll
    for (int mi = 0; mi < 4; mi++)
#pragma unroll
        for (int ni = 0; ni < 4; ni++)
#pragma unroll
            for (int j = 0; j < 4; j++) acc[mi][ni][j] = 0.f;

    gt_issue<MODE>(sb, 0, 0, Ap, Wp, t);

#pragma unroll 1
    for (int c = 0; c < 16; c++) {
        if (c + 1 < 16) {
            gt_issue<MODE>(sb, (c + 1) & 1, c + 1, Ap, Wp, t);
            CP_WAIT(1);
        } else {
            CP_WAIT(0);
        }
        __syncthreads();

        const float* As = sm + (c & 1) * STAGE_F;
        const float* Bs = As + B_OFF;
#pragma unroll
        for (int ks = 0; ks < 4; ks++) {
            const int kk = ks * 8 + tg;
            uint32_t a[4][4], b[4][2];
#pragma unroll
            for (int ni = 0; ni < 4; ni++) {
                const int n0 = wn + ni * 8 + g;
                b[ni][0] = *(const uint32_t*)&Bs[kk * B_PAD + n0];
                b[ni][1] = *(const uint32_t*)&Bs[(kk + 4) * B_PAD + n0];
            }
#pragma unroll
            for (int mi = 0; mi < 4; mi++) {
                const int m0 = wm + mi * 16 + g;
                if (MODE == 0) {
                    a[mi][0] = *(const uint32_t*)&As[kk * A_K_PAD + m0];
                    a[mi][1] = *(const uint32_t*)&As[kk * A_K_PAD + m0 + 8];
                    a[mi][2] = *(const uint32_t*)&As[(kk + 4) * A_K_PAD + m0];
                    a[mi][3] = *(const uint32_t*)&As[(kk + 4) * A_K_PAD + m0 + 8];
                } else {
                    a[mi][0] = *(const uint32_t*)&As[m0 * A_M_PAD + kk];
                    a[mi][1] = *(const uint32_t*)&As[(m0 + 8) * A_M_PAD + kk];
                    a[mi][2] = *(const uint32_t*)&As[m0 * A_M_PAD + kk + 4];
                    a[mi][3] = *(const uint32_t*)&As[(m0 + 8) * A_M_PAD + kk + 4];
                }
            }
#pragma unroll
            for (int mi = 0; mi < 4; mi++)
#pragma unroll
                for (int ni = 0; ni < 4; ni++)
                    mma_tf32(acc[mi][ni], a[mi], b[ni]);
        }
        __syncthreads();
    }

    // epilogue: + bias, fp32 out
#pragma unroll
    for (int ni = 0; ni < 4; ni++) {
        const int cb = bx * 128 + wn + ni * 8 + 2 * tg;
        const float2 bv = *(const float2*)&bias[cb];
#pragma unroll
        for (int mi = 0; mi < 4; mi++) {
            const int r0 = rowbase + wm + mi * 16 + g;
            float2 o0, o1;
            o0.x = acc[mi][ni][0] + bv.x;
            o0.y = acc[mi][ni][1] + bv.y;
            o1.x = acc[mi][ni][2] + bv.x;
            o1.y = acc[mi][ni][3] + bv.y;
            *(float2*)&C[(size_t)r0 * 512 + cb] = o0;
            *(float2*)&C[(size_t)(r0 + 8) * 512 + cb] = o1;
        }
    }
}

// ---------------------------------------------------------------------------
// Attention (exact fp32 f32x2): block = (b, h, 64-query tile), 512 threads /
// 16 warps, 4 q-rows per warp. smem: Qs^T[64d][65], Ks^T[64d][257],
// Vs[256][64]; weights alias Ks. Epilogue rounds output to tf32 (O-GEMM input).
// ---------------------------------------------------------------------------
#define ATTN_SMEM_BYTES ((64 * 65 + 64 * 257 + 256 * 64) * 4)

__global__ void __launch_bounds__(512, 1) attn_kernel() {
    extern __shared__ float sm[];
    float* Qs = sm;                 // 64*65
    float* Ks = sm + 64 * 65;       // 64*257
    float* Vs = Ks + 64 * 257;      // 256*64
    float* Ws = Ks;                 // alias after score phase

    const int bh = blockIdx.x;
    const int b = bh >> 3, h = bh & 7;
    const int q0 = blockIdx.y << 6;
    const int t = threadIdx.x;

    const float* qb = g_q + (size_t)b * (HW * CA) + (size_t)q0 * CA + h * HD;
    const float* kb = g_k + (size_t)b * (KL * CA) + h * HD;
    const float* vb = g_v + (size_t)b * (KL * CA) + h * HD;

#pragma unroll
    for (int r = 0; r < 8; r++) {        // Q tile, transposed store
        const int e = t + 512 * r;
        const int qq = e >> 6, d = e & 63;
        Qs[d * 65 + qq] = qb[(size_t)qq * CA + d];
    }
#pragma unroll 8
    for (int r = 0; r < 32; r++) {       // K tile, transposed store
        const int e = t + 512 * r;
        const int kk = e >> 6, d = e & 63;
        Ks[d * 257 + kk] = kb[(size_t)kk * CA + d];
    }
#pragma unroll
    for (int r = 0; r < 8; r++) {        // V tile, direct
        const int u = t + 512 * r;
        const int kk = u >> 4, d4 = (u & 15) << 2;
        *(float4*)&Vs[kk * 64 + d4] = *(const float4*)&vb[(size_t)kk * CA + d4];
    }
    __syncthreads();

    const int warp = t >> 5, lane = t & 31;

    // --- scores: S[4q][8k per lane] = Q @ K^T ---
    unsigned long long s2[4][4];
#pragma unroll
    for (int i = 0; i < 4; i++)
#pragma unroll
        for (int j = 0; j < 4; j++) s2[i][j] = 0ULL;

#pragma unroll 1
    for (int kk = 0; kk < 64; kk++) {
        const float* kr = Ks + kk * 257 + lane;
        const float* qr = Qs + kk * 65 + warp * 4;
        unsigned long long b2[4];
#pragma unroll
        for (int j = 0; j < 4; j++) b2[j] = pack2(kr[64 * j], kr[64 * j + 32]);
#pragma unroll
        for (int i = 0; i < 4; i++) {
            const float a = qr[i];
            const unsigned long long ad = pack2(a, a);
#pragma unroll
            for (int j = 0; j < 4; j++) s2[i][j] = ffma2(ad, b2[j], s2[i][j]);
        }
    }
    __syncthreads();   // all warps done reading Ks (Ws aliases it)

    // --- softmax (scale = 0.125) ---
#pragma unroll
    for (int i = 0; i < 4; i++) {
        float2 e[4];
        float m = -1e30f;
#pragma unroll
        for (int j = 0; j < 4; j++) {
            e[j] = unpack2(s2[i][j]);
            m = fmaxf(m, fmaxf(e[j].x, e[j].y));
        }
#pragma unroll
        for (int off = 16; off > 0; off >>= 1)
            m = fmaxf(m, __shfl_xor_sync(0xffffffffu, m, off));
        float sum = 0.f;
#pragma unroll
        for (int j = 0; j < 4; j++) {
            e[j].x = __expf(0.125f * (e[j].x - m));
            e[j].y = __expf(0.125f * (e[j].y - m));
            sum += e[j].x + e[j].y;
        }
#pragma unroll
        for (int off = 16; off > 0; off >>= 1)
            sum += __shfl_xor_sync(0xffffffffu, sum, off);
        const float inv = __frcp_rn(sum);
        float* wrow = Ws + (size_t)(warp * 4 + i) * 256 + lane;
#pragma unroll
        for (int j = 0; j < 4; j++) {
            wrow[64 * j] = e[j].x * inv;
            wrow[64 * j + 32] = e[j].y * inv;
        }
    }
    __syncthreads();

    // --- AV: O[4q][2d per lane] = W @ V ---
    unsigned long long o2[4];
#pragma unroll
    for (int i = 0; i < 4; i++) o2[i] = 0ULL;
#pragma unroll 2
    for (int k = 0; k < 256; k++) {
        const unsigned long long v2 =
            pack2(Vs[k * 64 + lane], Vs[k * 64 + lane + 32]);
        const float* wr = Ws + (size_t)(warp * 4) * 256 + k;
#pragma unroll
        for (int i = 0; i < 4; i++) {
            const float w = wr[i * 256];
            o2[i] = ffma2(pack2(w, w), v2, o2[i]);
        }
    }
    float* ob = g_attn + (size_t)b * (HW * CA) + (size_t)(q0 + warp * 4) * CA + h * HD;
#pragma unroll
    for (int i = 0; i < 4; i++) {
        const float2 f = unpack2(o2[i]);
        ob[(size_t)i * CA + lane] = cvt_tf32(f.x);        // tf32 round for O GEMM
        ob[(size_t)i * CA + lane + 32] = cvt_tf32(f.y);
    }
}

// ---------------------------------------------------------------------------
// Residual + LayerNorm + transpose to [b, c, h, w].
// ---------------------------------------------------------------------------
#define LN_SMEM_BYTES (32 * 513 * 4)

__global__ void __launch_bounds__(256, 1)
ln_kernel(const float* __restrict__ img, const float* __restrict__ gamma,
          const float* __restrict__ beta, float* __restrict__ out) {
    extern __shared__ float sm[];   // [32][513]
    __shared__ float smu[32], srv[32];
    const int b = blockIdx.x >> 5;
    const int s0 = (blockIdx.x & 31) << 5;
    const int t = threadIdx.x;

#pragma unroll
    for (int r = 0; r < 16; r++) {
        const int u = t + 256 * r;
        const int s = u >> 7, c4 = (u & 127) << 2;
        const float4 v = *(const float4*)&g_y[((size_t)(b * HW + s0 + s)) * CI + c4];
        float* dst = sm + s * 513 + c4;
        dst[0] = v.x; dst[1] = v.y; dst[2] = v.z; dst[3] = v.w;
    }
    __syncthreads();
#pragma unroll 8
    for (int r = 0; r < 64; r++) {
        const int u = t + 256 * r;
        const int c = u >> 5, s = u & 31;
        sm[s * 513 + c] += img[(size_t)b * (CI * HW) + (size_t)c * HW + s0 + s];
    }
    __syncthreads();

    const int warp = t >> 5, lane = t & 31;
#pragma unroll
    for (int rr = 0; rr < 4; rr++) {
        const int s = warp * 4 + rr;
        const float* row = sm + s * 513;
        float sum = 0.f;
#pragma unroll
        for (int i = 0; i < 16; i++) sum += row[lane + 32 * i];
#pragma unroll
        for (int off = 16; off > 0; off >>= 1)
            sum += __shfl_xor_sync(0xffffffffu, sum, off);
        const float mu = sum * (1.0f / 512.0f);
        float var = 0.f;
#pragma unroll
        for (int i = 0; i < 16; i++) {
            const float d = row[lane + 32 * i] - mu;
            var += d * d;
        }
#pragma unroll
        for (int off = 16; off > 0; off >>= 1)
            var += __shfl_xor_sync(0xffffffffu, var, off);
        var *= (1.0f / 512.0f);
        if (lane == 0) { smu[s] = mu; srv[s] = rsqrtf(var + 1e-5f); }
    }
    __syncthreads();

    const float mu = smu[lane], rv = srv[lane];
#pragma unroll 4
    for (int ci = 0; ci < 64; ci++) {
        const int c = warp * 64 + ci;
        const float val = (sm[lane * 513 + c] - mu) * rv * gamma[c] + beta[c];
        out[(size_t)b * (CI * HW) + (size_t)c * HW + s0 + lane] = val;
    }
}

// ---------------------------------------------------------------------------
extern "C" void kernel_launch(void* const* d_in, const int* in_sizes, int n_in,
                              void* d_out, int out_size) {
    (void)in_sizes; (void)n_in; (void)out_size;
    const float* img   = (const float*)d_in[0];
    const float* aud   = (const float*)d_in[1];
    const float* Wq    = (const float*)d_in[2];
    const float* bq    = (const float*)d_in[3];
    const float* Wk    = (const float*)d_in[4];
    const float* bk    = (const float*)d_in[5];
    const float* Wv    = (const float*)d_in[6];
    const float* bv    = (const float*)d_in[7];
    const float* Wo    = (const float*)d_in[8];
    const float* bo    = (const float*)d_in[9];
    const float* gamma = (const float*)d_in[10];
    const float* beta  = (const float*)d_in[11];
    float* out = (float*)d_out;

    cudaFuncSetAttribute((const void*)gemm_tc<0>,
                         cudaFuncAttributeMaxDynamicSharedMemorySize, GT_SMEM_BYTES);
    cudaFuncSetAttribute((const void*)gemm_tc<1>,
                         cudaFuncAttributeMaxDynamicSharedMemorySize, GT_SMEM_BYTES);
    cudaFuncSetAttribute((const void*)gemm_tc<2>,
                         cudaFuncAttributeMaxDynamicSharedMemorySize, GT_SMEM_BYTES);
    cudaFuncSetAttribute((const void*)gemm_tc<3>,
                         cudaFuncAttributeMaxDynamicSharedMemorySize, GT_SMEM_BYTES);
    cudaFuncSetAttribute((const void*)attn_kernel,
                         cudaFuncAttributeMaxDynamicSharedMemorySize, ATTN_SMEM_BYTES);
    cudaFuncSetAttribute((const void*)ln_kernel,
                         cudaFuncAttributeMaxDynamicSharedMemorySize, LN_SMEM_BYTES);

    float *imgr = nullptr, *audr = nullptr, *wr = nullptr;
    cudaGetSymbolAddress((void**)&imgr, g_imgr);
    cudaGetSymbolAddress((void**)&audr, g_audr);
    cudaGetSymbolAddress((void**)&wr, g_wr);

    // tf32 rounding of GEMM inputs (rna, unbiased)
    const int IMG_N4 = NB * CI * HW / 4;       // 2097152
    const int AUD_N4 = NB * KL * CA / 4;       //  524288
    const int W_N4 = 512 * 512 / 4;            //   65536
    round_tf32<<<IMG_N4 / 256, 256>>>((const float4*)img, (float4*)imgr, IMG_N4);
    round_tf32<<<AUD_N4 / 256, 256>>>((const float4*)aud, (float4*)audr, AUD_N4);
    round_tf32<<<W_N4 / 256, 256>>>((const float4*)Wq, (float4*)(wr + 0 * 512 * 512), W_N4);
    round_tf32<<<W_N4 / 256, 256>>>((const float4*)Wk, (float4*)(wr + 1 * 512 * 512), W_N4);
    round_tf32<<<W_N4 / 256, 256>>>((const float4*)Wv, (float4*)(wr + 2 * 512 * 512), W_N4);
    round_tf32<<<W_N4 / 256, 256>>>((const float4*)Wo, (float4*)(wr + 3 * 512 * 512), W_N4);

    gemm_tc<0><<<dim3(4, 128), 256, GT_SMEM_BYTES>>>(imgr, wr + 0 * 512 * 512, bq);
    gemm_tc<1><<<dim3(4, 32),  256, GT_SMEM_BYTES>>>(audr, wr + 1 * 512 * 512, bk);
    gemm_tc<2><<<dim3(4, 32),  256, GT_SMEM_BYTES>>>(audr, wr + 2 * 512 * 512, bv);
    attn_kernel<<<dim3(128, 16), 512, ATTN_SMEM_BYTES>>>();
    gemm_tc<3><<<dim3(4, 128), 256, GT_SMEM_BYTES>>>(nullptr, wr + 3 * 512 * 512, bo);
    ln_kernel<<<512, 256, LN_SMEM_BYTES>>>(img, gamma, beta, out);
}

// round 7
// speedup vs baseline: 3.3882x; 1.7734x over previous
#include <cuda_runtime.h>
#include <cuda_fp16.h>
#include <cstdint>

#define NB 16
#define HW 1024
#define CI 512
#define CA 512
#define KL 256
#define HD 64

// Scratch (alloc-free: __device__ globals)
__device__ float g_q[NB * HW * CA];      // tf32-rounded by Q GEMM epilogue
__device__ float g_k[NB * KL * CA];      // tf32-rounded by K GEMM epilogue
__device__ float g_v[NB * KL * CA];      // fp32 (converted to fp16 in attn)
__device__ float g_attn[NB * HW * CA];   // tf32-rounded by attn epilogue
__device__ float g_y[NB * HW * CI];
__device__ float g_imgr[NB * CI * HW];   // tf32-rounded img
__device__ float g_audr[NB * KL * CA];   // tf32-rounded audio
__device__ float g_wr[4 * 512 * 512];    // tf32-rounded weights (orig [K][N])

// ---------------------------------------------------------------------------
// Helpers
// ---------------------------------------------------------------------------
__device__ __forceinline__ uint32_t smem_u32(const void* p) {
    uint32_t a;
    asm("{ .reg .u64 t; cvta.to.shared.u64 t, %1; cvt.u32.u64 %0, t; }"
        : "=r"(a) : "l"(p));
    return a;
}
__device__ __forceinline__ float cvt_tf32(float x) {
    uint32_t r;
    asm("cvt.rna.tf32.f32 %0, %1;" : "=r"(r) : "f"(x));
    return __uint_as_float(r);
}
#define CP_ASYNC16(dst, src) \
    asm volatile("cp.async.cg.shared.global [%0], [%1], 16;" \
                 :: "r"(dst), "l"(src) : "memory")
#define CP_COMMIT() asm volatile("cp.async.commit_group;" ::: "memory")
#define CP_WAIT(n)  asm volatile("cp.async.wait_group %0;" :: "n"(n) : "memory")

__device__ __forceinline__ void mma_tf32(float (&c)[4], const uint32_t (&a)[4],
                                         const uint32_t (&b)[2]) {
    asm volatile(
        "mma.sync.aligned.m16n8k8.row.col.f32.tf32.tf32.f32 "
        "{%0,%1,%2,%3}, {%4,%5,%6,%7}, {%8,%9}, {%0,%1,%2,%3};"
        : "+f"(c[0]), "+f"(c[1]), "+f"(c[2]), "+f"(c[3])
        : "r"(a[0]), "r"(a[1]), "r"(a[2]), "r"(a[3]), "r"(b[0]), "r"(b[1]));
}
__device__ __forceinline__ void mma_f16(float (&c)[4], const uint32_t (&a)[4],
                                        const uint32_t (&b)[2]) {
    asm volatile(
        "mma.sync.aligned.m16n8k16.row.col.f32.f16.f16.f32 "
        "{%0,%1,%2,%3}, {%4,%5,%6,%7}, {%8,%9}, {%0,%1,%2,%3};"
        : "+f"(c[0]), "+f"(c[1]), "+f"(c[2]), "+f"(c[3])
        : "r"(a[0]), "r"(a[1]), "r"(a[2]), "r"(a[3]), "r"(b[0]), "r"(b[1]));
}

// ---------------------------------------------------------------------------
// tf32 pre-rounding (unbiased rna)
// ---------------------------------------------------------------------------
__global__ void round_tf32(const float4* __restrict__ src,
                           float4* __restrict__ dst, int n4) {
    const int i = blockIdx.x * blockDim.x + threadIdx.x;
    if (i < n4) {
        float4 v = src[i];
        v.x = cvt_tf32(v.x); v.y = cvt_tf32(v.y);
        v.z = cvt_tf32(v.z); v.w = cvt_tf32(v.w);
        dst[i] = v;
    }
}

// ---------------------------------------------------------------------------
// tf32 mma.sync GEMM: C[M,512] = A[M,512] @ W[512,512] + bias
// 128x128 tile, BK=32, 256 threads (8 warps, 2m x 4n), warp tile 64x32.
// MODE 0 (Q) / 1 (K): outputs rounded to tf32 (consumed by attn tf32 mma).
// ---------------------------------------------------------------------------
#define A_K_PAD 136
#define A_M_PAD 36
#define B_PAD 136
#define B_OFF 4608
#define STAGE_F 8960
#define GT_SMEM_BYTES (2 * STAGE_F * 4)

template <int MODE>
__device__ __forceinline__ void gt_issue(uint32_t sb, int stage, int kc,
                                         const float* __restrict__ Ap,
                                         const float* __restrict__ Wp, int t) {
    const int k0 = kc * 32;
    const uint32_t abase = sb + (uint32_t)(stage * STAGE_F) * 4;
    const uint32_t bbase = abase + B_OFF * 4;
#pragma unroll
    for (int r = 0; r < 4; r++) {
        const int idx = t + 256 * r;
        if (MODE == 0) {
            const int k = idx >> 5, m4 = (idx & 31) << 2;
            CP_ASYNC16(abase + (uint32_t)(k * A_K_PAD + m4) * 4,
                       Ap + (size_t)(k0 + k) * HW + m4);
        } else {
            const int m = idx >> 3, k4 = (idx & 7) << 2;
            CP_ASYNC16(abase + (uint32_t)(m * A_M_PAD + k4) * 4,
                       Ap + (size_t)m * 512 + k0 + k4);
        }
    }
#pragma unroll
    for (int r = 0; r < 4; r++) {
        const int idx = t + 256 * r;
        const int k = idx >> 5, n4 = (idx & 31) << 2;
        CP_ASYNC16(bbase + (uint32_t)(k * B_PAD + n4) * 4,
                   Wp + (size_t)(k0 + k) * 512 + n4);
    }
    CP_COMMIT();
}

template <int MODE>
__global__ void __launch_bounds__(256)
gemm_tc(const float* __restrict__ A, const float* __restrict__ W,
        const float* __restrict__ bias) {
    extern __shared__ float sm[];
    const uint32_t sb = smem_u32(sm);
    const int t = threadIdx.x, warp = t >> 5, lane = t & 31;
    const int g = lane >> 2, tg = lane & 3;
    const int wm = (warp >> 2) * 64, wn = (warp & 3) * 32;
    const int bx = blockIdx.x, by = blockIdx.y;

    float* C = (MODE == 0) ? g_q : (MODE == 1) ? g_k : (MODE == 2) ? g_v : g_y;
    const float* Ap;
    int rowbase;
    if (MODE == 0) {
        Ap = A + (size_t)(by >> 3) * (CI * HW) + ((by & 7) << 7);
        rowbase = (by >> 3) * HW + ((by & 7) << 7);
    } else if (MODE == 3) {
        Ap = g_attn + (size_t)by * 128 * 512;
        rowbase = by * 128;
    } else {
        Ap = A + (size_t)by * 128 * 512;
        rowbase = by * 128;
    }
    const float* Wp = W + bx * 128;

    float acc[4][4][4];
#pragma unroll
    for (int mi = 0; mi < 4; mi++)
#pragma unroll
        for (int ni = 0; ni < 4; ni++)
#pragma unroll
            for (int j = 0; j < 4; j++) acc[mi][ni][j] = 0.f;

    gt_issue<MODE>(sb, 0, 0, Ap, Wp, t);

#pragma unroll 1
    for (int c = 0; c < 16; c++) {
        if (c + 1 < 16) {
            gt_issue<MODE>(sb, (c + 1) & 1, c + 1, Ap, Wp, t);
            CP_WAIT(1);
        } else {
            CP_WAIT(0);
        }
        __syncthreads();

        const float* As = sm + (c & 1) * STAGE_F;
        const float* Bs = As + B_OFF;
#pragma unroll
        for (int ks = 0; ks < 4; ks++) {
            const int kk = ks * 8 + tg;
            uint32_t a[4][4], b[4][2];
#pragma unroll
            for (int ni = 0; ni < 4; ni++) {
                const int n0 = wn + ni * 8 + g;
                b[ni][0] = *(const uint32_t*)&Bs[kk * B_PAD + n0];
                b[ni][1] = *(const uint32_t*)&Bs[(kk + 4) * B_PAD + n0];
            }
#pragma unroll
            for (int mi = 0; mi < 4; mi++) {
                const int m0 = wm + mi * 16 + g;
                if (MODE == 0) {
                    a[mi][0] = *(const uint32_t*)&As[kk * A_K_PAD + m0];
                    a[mi][1] = *(const uint32_t*)&As[kk * A_K_PAD + m0 + 8];
                    a[mi][2] = *(const uint32_t*)&As[(kk + 4) * A_K_PAD + m0];
                    a[mi][3] = *(const uint32_t*)&As[(kk + 4) * A_K_PAD + m0 + 8];
                } else {
                    a[mi][0] = *(const uint32_t*)&As[m0 * A_M_PAD + kk];
                    a[mi][1] = *(const uint32_t*)&As[(m0 + 8) * A_M_PAD + kk];
                    a[mi][2] = *(const uint32_t*)&As[m0 * A_M_PAD + kk + 4];
                    a[mi][3] = *(const uint32_t*)&As[(m0 + 8) * A_M_PAD + kk + 4];
                }
            }
#pragma unroll
            for (int mi = 0; mi < 4; mi++)
#pragma unroll
                for (int ni = 0; ni < 4; ni++)
                    mma_tf32(acc[mi][ni], a[mi], b[ni]);
        }
        __syncthreads();
    }

    // epilogue: + bias; Q/K outputs rounded to tf32 for attention mma
    const bool RND = (MODE == 0 || MODE == 1);
#pragma unroll
    for (int ni = 0; ni < 4; ni++) {
        const int cb = bx * 128 + wn + ni * 8 + 2 * tg;
        const float2 bv = *(const float2*)&bias[cb];
#pragma unroll
        for (int mi = 0; mi < 4; mi++) {
            const int r0 = rowbase + wm + mi * 16 + g;
            float2 o0, o1;
            o0.x = acc[mi][ni][0] + bv.x;
            o0.y = acc[mi][ni][1] + bv.y;
            o1.x = acc[mi][ni][2] + bv.x;
            o1.y = acc[mi][ni][3] + bv.y;
            if (RND) {
                o0.x = cvt_tf32(o0.x); o0.y = cvt_tf32(o0.y);
                o1.x = cvt_tf32(o1.x); o1.y = cvt_tf32(o1.y);
            }
            *(float2*)&C[(size_t)r0 * 512 + cb] = o0;
            *(float2*)&C[(size_t)(r0 + 8) * 512 + cb] = o1;
        }
    }
}

// ---------------------------------------------------------------------------
// Tensor-core attention: block = (b,h) x 128 q-rows, 256 threads, 8 warps,
// 16 q-rows per warp.
//   S = Q K^T : tf32 m16n8k8, fp32 accum (Q,K pre-rounded to tf32)
//   softmax   : fp32 regs, quad shfl reductions
//   O = P V   : fp16 m16n8k16 — S-accum fragment packs directly into fp16
//               A fragment (cols 2tg,2tg+1); V as half2 key-pairs (B frag)
// smem: Qs[128][68] f32, Ks[256][68] f32, V2[128][72] half2 = 141,312 B
// ---------------------------------------------------------------------------
#define QS_OFF 0
#define KS_OFF (128 * 68)
#define V2_OFF (KS_OFF + 256 * 68)
#define ATTN_SMEM_BYTES ((V2_OFF + 128 * 72) * 4)

__global__ void __launch_bounds__(256, 1) attn_tc() {
    extern __shared__ float sm[];
    float* Qs = sm + QS_OFF;
    float* Ks = sm + KS_OFF;
    __half2* V2 = (__half2*)(sm + V2_OFF);

    const int b = blockIdx.x >> 3, h = blockIdx.x & 7;
    const int q0 = blockIdx.y << 7;
    const int t = threadIdx.x, warp = t >> 5, lane = t & 31;
    const int g = lane >> 2, tg = lane & 3;

    const float* qb = g_q + (size_t)(b * HW + q0) * CA + h * HD;
    const float* kb = g_k + (size_t)b * (KL * CA) + h * HD;
    const float* vb = g_v + (size_t)b * (KL * CA) + h * HD;

#pragma unroll
    for (int r = 0; r < 8; r++) {        // Q tile
        const int idx = t + 256 * r;
        const int row = idx >> 4, d4 = (idx & 15) << 2;
        *(float4*)&Qs[row * 68 + d4] = *(const float4*)&qb[(size_t)row * CA + d4];
    }
#pragma unroll
    for (int r = 0; r < 16; r++) {       // K tile
        const int idx = t + 256 * r;
        const int row = idx >> 4, d4 = (idx & 15) << 2;
        *(float4*)&Ks[row * 68 + d4] = *(const float4*)&kb[(size_t)row * CA + d4];
    }
#pragma unroll
    for (int r = 0; r < 32; r++) {       // V tile -> half2 key pairs
        const int idx = t + 256 * r;
        const int kp = idx >> 6, d = idx & 63;
        const float v0 = vb[(size_t)(2 * kp) * CA + d];
        const float v1 = vb[(size_t)(2 * kp + 1) * CA + d];
        V2[kp * 72 + d] = __floats2half2_rn(v0, v1);
    }
    __syncthreads();

    // Q fragments (reused across all 32 key octets)
    uint32_t qf[8][4];
    const float* qw = Qs + warp * 16 * 68;
#pragma unroll
    for (int kc = 0; kc < 8; kc++) {
        qf[kc][0] = __float_as_uint(qw[g * 68 + kc * 8 + tg]);
        qf[kc][1] = __float_as_uint(qw[(g + 8) * 68 + kc * 8 + tg]);
        qf[kc][2] = __float_as_uint(qw[g * 68 + kc * 8 + tg + 4]);
        qf[kc][3] = __float_as_uint(qw[(g + 8) * 68 + kc * 8 + tg + 4]);
    }

    // --- S = Q K^T ---
    float sc[32][4];
#pragma unroll
    for (int j = 0; j < 32; j++)
#pragma unroll
        for (int i = 0; i < 4; i++) sc[j][i] = 0.f;

#pragma unroll
    for (int j = 0; j < 32; j++) {       // key octet j: keys j*8 .. j*8+7
        const float* kr = Ks + (j * 8 + g) * 68;
#pragma unroll
        for (int kc = 0; kc < 8; kc++) {
            uint32_t bf[2];
            bf[0] = __float_as_uint(kr[kc * 8 + tg]);
            bf[1] = __float_as_uint(kr[kc * 8 + tg + 4]);
            mma_tf32(sc[j], qf[kc], bf);
        }
    }

    // --- softmax (rows g and g+8; scale = 0.125) ---
    uint32_t pl[32], ph[32];
    {
        float m0 = -1e30f, m1 = -1e30f;
#pragma unroll
        for (int j = 0; j < 32; j++) {
            m0 = fmaxf(m0, fmaxf(sc[j][0], sc[j][1]));
            m1 = fmaxf(m1, fmaxf(sc[j][2], sc[j][3]));
        }
        m0 = fmaxf(m0, __shfl_xor_sync(0xffffffffu, m0, 1));
        m0 = fmaxf(m0, __shfl_xor_sync(0xffffffffu, m0, 2));
        m1 = fmaxf(m1, __shfl_xor_sync(0xffffffffu, m1, 1));
        m1 = fmaxf(m1, __shfl_xor_sync(0xffffffffu, m1, 2));
        float s0 = 0.f, s1 = 0.f;
#pragma unroll
        for (int j = 0; j < 32; j++) {
            sc[j][0] = __expf(0.125f * (sc[j][0] - m0));
            sc[j][1] = __expf(0.125f * (sc[j][1] - m0));
            sc[j][2] = __expf(0.125f * (sc[j][2] - m1));
            sc[j][3] = __expf(0.125f * (sc[j][3] - m1));
            s0 += sc[j][0] + sc[j][1];
            s1 += sc[j][2] + sc[j][3];
        }
        s0 += __shfl_xor_sync(0xffffffffu, s0, 1);
        s0 += __shfl_xor_sync(0xffffffffu, s0, 2);
        s1 += __shfl_xor_sync(0xffffffffu, s1, 1);
        s1 += __shfl_xor_sync(0xffffffffu, s1, 2);
        const float i0 = __frcp_rn(s0), i1 = __frcp_rn(s1);
#pragma unroll
        for (int j = 0; j < 32; j++) {
            const __half2 lo = __floats2half2_rn(sc[j][0] * i0, sc[j][1] * i0);
            const __half2 hi = __floats2half2_rn(sc[j][2] * i1, sc[j][3] * i1);
            pl[j] = *(const uint32_t*)&lo;
            ph[j] = *(const uint32_t*)&hi;
        }
    }

    // --- O = P V (fp16 m16n8k16) ---
    float oc[8][4];
#pragma unroll
    for (int ni = 0; ni < 8; ni++)
#pragma unroll
        for (int i = 0; i < 4; i++) oc[ni][i] = 0.f;

#pragma unroll
    for (int kc = 0; kc < 16; kc++) {    // 16 keys per chunk
        uint32_t a[4];
        a[0] = pl[2 * kc];       // P[g][kc*16+2tg, +1]
        a[1] = ph[2 * kc];       // P[g+8][...]
        a[2] = pl[2 * kc + 1];   // P[g][kc*16+8+2tg, +1]
        a[3] = ph[2 * kc + 1];
        const __half2* vr0 = V2 + (kc * 8 + tg) * 72;
        const __half2* vr1 = V2 + (kc * 8 + tg + 4) * 72;
#pragma unroll
        for (int ni = 0; ni < 8; ni++) {
            uint32_t bf[2];
            bf[0] = *(const uint32_t*)&vr0[ni * 8 + g];
            bf[1] = *(const uint32_t*)&vr1[ni * 8 + g];
            mma_f16(oc[ni], a, bf);
        }
    }

    float* ob = g_attn + (size_t)(b * HW + q0 + warp * 16) * CA + h * HD;
#pragma unroll
    for (int ni = 0; ni < 8; ni++) {
        const int col = ni * 8 + 2 * tg;
        float2 o0, o1;
        o0.x = cvt_tf32(oc[ni][0]); o0.y = cvt_tf32(oc[ni][1]);
        o1.x = cvt_tf32(oc[ni][2]); o1.y = cvt_tf32(oc[ni][3]);
        *(float2*)&ob[(size_t)g * CA + col] = o0;
        *(float2*)&ob[(size_t)(g + 8) * CA + col] = o1;
    }
}

// ---------------------------------------------------------------------------
// Residual + LayerNorm + transpose to [b, c, h, w].
// ---------------------------------------------------------------------------
#define LN_SMEM_BYTES (32 * 513 * 4)

__global__ void __launch_bounds__(256, 1)
ln_kernel(const float* __restrict__ img, const float* __restrict__ gamma,
          const float* __restrict__ beta, float* __restrict__ out) {
    extern __shared__ float sm[];   // [32][513]
    __shared__ float smu[32], srv[32];
    const int b = blockIdx.x >> 5;
    const int s0 = (blockIdx.x & 31) << 5;
    const int t = threadIdx.x;

#pragma unroll
    for (int r = 0; r < 16; r++) {
        const int u = t + 256 * r;
        const int s = u >> 7, c4 = (u & 127) << 2;
        const float4 v = *(const float4*)&g_y[((size_t)(b * HW + s0 + s)) * CI + c4];
        float* dst = sm + s * 513 + c4;
        dst[0] = v.x; dst[1] = v.y; dst[2] = v.z; dst[3] = v.w;
    }
    __syncthreads();
#pragma unroll 8
    for (int r = 0; r < 64; r++) {
        const int u = t + 256 * r;
        const int c = u >> 5, s = u & 31;
        sm[s * 513 + c] += img[(size_t)b * (CI * HW) + (size_t)c * HW + s0 + s];
    }
    __syncthreads();

    const int warp = t >> 5, lane = t & 31;
#pragma unroll
    for (int rr = 0; rr < 4; rr++) {
        const int s = warp * 4 + rr;
        const float* row = sm + s * 513;
        float sum = 0.f;
#pragma unroll
        for (int i = 0; i < 16; i++) sum += row[lane + 32 * i];
#pragma unroll
        for (int off = 16; off > 0; off >>= 1)
            sum += __shfl_xor_sync(0xffffffffu, sum, off);
        const float mu = sum * (1.0f / 512.0f);
        float var = 0.f;
#pragma unroll
        for (int i = 0; i < 16; i++) {
            const float d = row[lane + 32 * i] - mu;
            var += d * d;
        }
#pragma unroll
        for (int off = 16; off > 0; off >>= 1)
            var += __shfl_xor_sync(0xffffffffu, var, off);
        var *= (1.0f / 512.0f);
        if (lane == 0) { smu[s] = mu; srv[s] = rsqrtf(var + 1e-5f); }
    }
    __syncthreads();

    const float mu = smu[lane], rv = srv[lane];
#pragma unroll 4
    for (int ci = 0; ci < 64; ci++) {
        const int c = warp * 64 + ci;
        const float val = (sm[lane * 513 + c] - mu) * rv * gamma[c] + beta[c];
        out[(size_t)b * (CI * HW) + (size_t)c * HW + s0 + lane] = val;
    }
}

// ---------------------------------------------------------------------------
extern "C" void kernel_launch(void* const* d_in, const int* in_sizes, int n_in,
                              void* d_out, int out_size) {
    (void)in_sizes; (void)n_in; (void)out_size;
    const float* img   = (const float*)d_in[0];
    const float* aud   = (const float*)d_in[1];
    const float* Wq    = (const float*)d_in[2];
    const float* bq    = (const float*)d_in[3];
    const float* Wk    = (const float*)d_in[4];
    const float* bk    = (const float*)d_in[5];
    const float* Wv    = (const float*)d_in[6];
    const float* bv    = (const float*)d_in[7];
    const float* Wo    = (const float*)d_in[8];
    const float* bo    = (const float*)d_in[9];
    const float* gamma = (const float*)d_in[10];
    const float* beta  = (const float*)d_in[11];
    float* out = (float*)d_out;

    cudaFuncSetAttribute((const void*)gemm_tc<0>,
                         cudaFuncAttributeMaxDynamicSharedMemorySize, GT_SMEM_BYTES);
    cudaFuncSetAttribute((const void*)gemm_tc<1>,
                         cudaFuncAttributeMaxDynamicSharedMemorySize, GT_SMEM_BYTES);
    cudaFuncSetAttribute((const void*)gemm_tc<2>,
                         cudaFuncAttributeMaxDynamicSharedMemorySize, GT_SMEM_BYTES);
    cudaFuncSetAttribute((const void*)gemm_tc<3>,
                         cudaFuncAttributeMaxDynamicSharedMemorySize, GT_SMEM_BYTES);
    cudaFuncSetAttribute((const void*)attn_tc,
                         cudaFuncAttributeMaxDynamicSharedMemorySize, ATTN_SMEM_BYTES);
    cudaFuncSetAttribute((const void*)ln_kernel,
                         cudaFuncAttributeMaxDynamicSharedMemorySize, LN_SMEM_BYTES);

    float *imgr = nullptr, *audr = nullptr, *wr = nullptr;
    cudaGetSymbolAddress((void**)&imgr, g_imgr);
    cudaGetSymbolAddress((void**)&audr, g_audr);
    cudaGetSymbolAddress((void**)&wr, g_wr);

    // tf32 rounding of GEMM inputs (rna, unbiased)
    const int IMG_N4 = NB * CI * HW / 4;
    const int AUD_N4 = NB * KL * CA / 4;
    const int W_N4 = 512 * 512 / 4;
    round_tf32<<<IMG_N4 / 256, 256>>>((const float4*)img, (float4*)imgr, IMG_N4);
    round_tf32<<<AUD_N4 / 256, 256>>>((const float4*)aud, (float4*)audr, AUD_N4);
    round_tf32<<<W_N4 / 256, 256>>>((const float4*)Wq, (float4*)(wr + 0 * 512 * 512), W_N4);
    round_tf32<<<W_N4 / 256, 256>>>((const float4*)Wk, (float4*)(wr + 1 * 512 * 512), W_N4);
    round_tf32<<<W_N4 / 256, 256>>>((const float4*)Wv, (float4*)(wr + 2 * 512 * 512), W_N4);
    round_tf32<<<W_N4 / 256, 256>>>((const float4*)Wo, (float4*)(wr + 3 * 512 * 512), W_N4);

    gemm_tc<0><<<dim3(4, 128), 256, GT_SMEM_BYTES>>>(imgr, wr + 0 * 512 * 512, bq);
    gemm_tc<1><<<dim3(4, 32),  256, GT_SMEM_BYTES>>>(audr, wr + 1 * 512 * 512, bk);
    gemm_tc<2><<<dim3(4, 32),  256, GT_SMEM_BYTES>>>(audr, wr + 2 * 512 * 512, bv);
    attn_tc<<<dim3(128, 8), 256, ATTN_SMEM_BYTES>>>();
    gemm_tc<3><<<dim3(4, 128), 256, GT_SMEM_BYTES>>>(nullptr, wr + 3 * 512 * 512, bo);
    ln_kernel<<<512, 256, LN_SMEM_BYTES>>>(img, gamma, beta, out);
}

// round 9
// speedup vs baseline: 4.9186x; 1.4517x over previous
#include <cuda_runtime.h>
#include <cuda_fp16.h>
#include <cstdint>

#define NB 16
#define HW 1024
#define CI 512
#define CA 512
#define KL 256

// Scratch (alloc-free: __device__ globals)
__device__ __half g_qh[NB * HW * CA];     // Q (half, from Q GEMM)
__device__ __half g_kh[NB * KL * CA];     // K
__device__ __half g_vh[NB * KL * CA];     // V
__device__ __half g_attnh[NB * HW * CA];  // attention out (half)
__device__ float  g_y[NB * HW * CI];      // O GEMM out (fp32, LN input)
__device__ __half g_imgth[NB * HW * CI];  // img transposed [b][s][c], half
__device__ __half g_audh[NB * KL * CA];   // audio, half
__device__ __half g_wth[4 * 512 * 512];   // weights transposed [n][k], half

// ---------------------------------------------------------------------------
// Helpers
// ---------------------------------------------------------------------------
__device__ __forceinline__ uint32_t smem_u32(const void* p) {
    uint32_t a;
    asm("{ .reg .u64 t; cvta.to.shared.u64 t, %1; cvt.u32.u64 %0, t; }"
        : "=r"(a) : "l"(p));
    return a;
}
#define CP_ASYNC16(dst, src) \
    asm volatile("cp.async.cg.shared.global [%0], [%1], 16;" \
                 :: "r"(dst), "l"(src) : "memory")
#define CP_COMMIT() asm volatile("cp.async.commit_group;" ::: "memory")
#define CP_WAIT(n)  asm volatile("cp.async.wait_group %0;" :: "n"(n) : "memory")

__device__ __forceinline__ void mma_f16(float (&c)[4], const uint32_t (&a)[4],
                                        const uint32_t (&b)[2]) {
    asm volatile(
        "mma.sync.aligned.m16n8k16.row.col.f32.f16.f16.f32 "
        "{%0,%1,%2,%3}, {%4,%5,%6,%7}, {%8,%9}, {%0,%1,%2,%3};"
        : "+f"(c[0]), "+f"(c[1]), "+f"(c[2]), "+f"(c[3])
        : "r"(a[0]), "r"(a[1]), "r"(a[2]), "r"(a[3]), "r"(b[0]), "r"(b[1]));
}

// ---------------------------------------------------------------------------
// Converters
// ---------------------------------------------------------------------------
// img [b][c][s] fp32 -> [b][s][c] half (transpose through smem)
__global__ void cvt_img_t(const float* __restrict__ img) {
    __shared__ float tile[32][33];
    const int c0 = blockIdx.x * 32, s0 = blockIdx.y * 32, b = blockIdx.z;
    const int tx = threadIdx.x, ty = threadIdx.y;
#pragma unroll
    for (int i = 0; i < 4; i++)
        tile[ty + 8 * i][tx] =
            img[((size_t)b * CI + c0 + ty + 8 * i) * HW + s0 + tx];
    __syncthreads();
#pragma unroll
    for (int i = 0; i < 4; i++)
        g_imgth[((size_t)b * HW + s0 + ty + 8 * i) * CI + c0 + tx] =
            __float2half(tile[tx][ty + 8 * i]);
}

// W [k][n] fp32 -> g_wth[z][n][k] half (transpose)
__global__ void cvt_w_t(const float* __restrict__ W0,
                        const float* __restrict__ W1,
                        const float* __restrict__ W2,
                        const float* __restrict__ W3) {
    __shared__ float tile[32][33];
    const int z = blockIdx.z;
    const float* W = (z == 0) ? W0 : (z == 1) ? W1 : (z == 2) ? W2 : W3;
    __half* T = g_wth + (size_t)z * 512 * 512;
    const int n0 = blockIdx.x * 32, k0 = blockIdx.y * 32;
    const int tx = threadIdx.x, ty = threadIdx.y;
#pragma unroll
    for (int i = 0; i < 4; i++)
        tile[ty + 8 * i][tx] = W[(size_t)(k0 + ty + 8 * i) * 512 + n0 + tx];
    __syncthreads();
#pragma unroll
    for (int i = 0; i < 4; i++)
        T[(size_t)(n0 + ty + 8 * i) * 512 + k0 + tx] = __float2half(tile[tx][ty + 8 * i]);
}

// audio fp32 -> half, elementwise
__global__ void cvt_aud(const float4* __restrict__ src) {
    const int i = blockIdx.x * blockDim.x + threadIdx.x;
    const float4 v = src[i];
    __half2* dst = (__half2*)g_audh;
    dst[2 * i] = __floats2half2_rn(v.x, v.y);
    dst[2 * i + 1] = __floats2half2_rn(v.z, v.w);
}

// ---------------------------------------------------------------------------
// HGEMM: C[M,512] = A[M,512] @ Wt^T + bias   (A row-major half, Wt [n][k] half)
// 128x128 tile, BK=64, 256 threads (8 warps 2m x 4n), warp tile 64x32,
// m16n8k16 fp16 MMA, fp32 accum, 2-stage cp.async.
// smem per matrix per stage: [128 rows][36 half2] (32 data + 4 pad).
// MODE 0: A=g_imgth -> g_qh (half)   1: g_audh -> g_kh   2: g_audh -> g_vh
// MODE 3: A=g_attnh -> g_y (fp32)
// ---------------------------------------------------------------------------
#define HP 36
#define AB_U32 (128 * HP)          // 4608 uint32 per matrix per stage
#define STAGE_U32 (2 * AB_U32)     // 9216
#define GT_SMEM_BYTES (2 * STAGE_U32 * 4)   // 73728

__device__ __forceinline__ void gt_issue(uint32_t sb, int stage, int kc,
                                         const __half* __restrict__ Ap,
                                         const __half* __restrict__ Bp, int t) {
    const int k0 = kc * 64;
    const uint32_t abase = sb + (uint32_t)(stage * STAGE_U32) * 4;
    const uint32_t bbase = abase + AB_U32 * 4;
#pragma unroll
    for (int r = 0; r < 4; r++) {
        const int idx = t + 256 * r;
        const int row = idx >> 3, j = idx & 7;
        CP_ASYNC16(abase + (uint32_t)(row * HP + 4 * j) * 4,
                   Ap + (size_t)row * 512 + k0 + 8 * j);
    }
#pragma unroll
    for (int r = 0; r < 4; r++) {
        const int idx = t + 256 * r;
        const int row = idx >> 3, j = idx & 7;
        CP_ASYNC16(bbase + (uint32_t)(row * HP + 4 * j) * 4,
                   Bp + (size_t)row * 512 + k0 + 8 * j);
    }
    CP_COMMIT();
}

template <int MODE>
__global__ void __launch_bounds__(256)
gemm_h(const float* __restrict__ bias) {
    extern __shared__ uint32_t smu[];
    const uint32_t sb = smem_u32(smu);
    const int t = threadIdx.x, warp = t >> 5, lane = t & 31;
    const int g = lane >> 2, tg = lane & 3;
    const int wm = (warp >> 2) * 64, wn = (warp & 3) * 32;
    const int bx = blockIdx.x, by = blockIdx.y;

    const __half* Ap =
        ((MODE == 0) ? g_imgth : (MODE == 3) ? g_attnh : g_audh) +
        (size_t)by * 128 * 512;
    const __half* Bp = g_wth + (size_t)MODE * 512 * 512 + (size_t)bx * 128 * 512;

    float acc[4][4][4];
#pragma unroll
    for (int mi = 0; mi < 4; mi++)
#pragma unroll
        for (int ni = 0; ni < 4; ni++)
#pragma unroll
            for (int j = 0; j < 4; j++) acc[mi][ni][j] = 0.f;

    gt_issue(sb, 0, 0, Ap, Bp, t);

#pragma unroll 1
    for (int c = 0; c < 8; c++) {
        if (c + 1 < 8) {
            gt_issue(sb, (c + 1) & 1, c + 1, Ap, Bp, t);
            CP_WAIT(1);
        } else {
            CP_WAIT(0);
        }
        __syncthreads();

        const uint32_t* As = smu + (c & 1) * STAGE_U32;
        const uint32_t* Bs = As + AB_U32;
#pragma unroll
        for (int ks = 0; ks < 4; ks++) {
            const int hk = ks * 8 + tg;
            uint32_t a[4][4], b[4][2];
#pragma unroll
            for (int ni = 0; ni < 4; ni++) {
                const uint32_t* br = Bs + (wn + ni * 8 + g) * HP;
                b[ni][0] = br[hk];
                b[ni][1] = br[hk + 4];
            }
#pragma unroll
            for (int mi = 0; mi < 4; mi++) {
                const uint32_t* ar0 = As + (wm + mi * 16 + g) * HP;
                const uint32_t* ar1 = ar0 + 8 * HP;
                a[mi][0] = ar0[hk];
                a[mi][1] = ar1[hk];
                a[mi][2] = ar0[hk + 4];
                a[mi][3] = ar1[hk + 4];
            }
#pragma unroll
            for (int mi = 0; mi < 4; mi++)
#pragma unroll
                for (int ni = 0; ni < 4; ni++)
                    mma_f16(acc[mi][ni], a[mi], b[ni]);
        }
        __syncthreads();
    }

    // epilogue
    const int rowbase = by * 128;
#pragma unroll
    for (int ni = 0; ni < 4; ni++) {
        const int cb = bx * 128 + wn + ni * 8 + 2 * tg;
        const float2 bv = *(const float2*)&bias[cb];
#pragma unroll
        for (int mi = 0; mi < 4; mi++) {
            const int r0 = rowbase + wm + mi * 16 + g;
            if (MODE == 3) {
                float2 o0, o1;
                o0.x = acc[mi][ni][0] + bv.x; o0.y = acc[mi][ni][1] + bv.y;
                o1.x = acc[mi][ni][2] + bv.x; o1.y = acc[mi][ni][3] + bv.y;
                *(float2*)&g_y[(size_t)r0 * 512 + cb] = o0;
                *(float2*)&g_y[(size_t)(r0 + 8) * 512 + cb] = o1;
            } else {
                __half* C = (MODE == 0) ? g_qh : (MODE == 1) ? g_kh : g_vh;
                const __half2 h0 =
                    __floats2half2_rn(acc[mi][ni][0] + bv.x, acc[mi][ni][1] + bv.y);
                const __half2 h1 =
                    __floats2half2_rn(acc[mi][ni][2] + bv.x, acc[mi][ni][3] + bv.y);
                *(__half2*)&C[(size_t)r0 * 512 + cb] = h0;
                *(__half2*)&C[(size_t)(r0 + 8) * 512 + cb] = h1;
            }
        }
    }
}

// ---------------------------------------------------------------------------
// Tensor-core attention (all fp16 inputs, fp32 accum/softmax):
// block = (b,h) x 128 q-rows, 256 threads, 8 warps, 16 q-rows/warp.
//   S = Q K^T : fp16 m16n8k16
//   softmax   : fp32 regs, quad shfl
//   O = P V   : fp16 m16n8k16, S-fragment packs directly into A-fragment
// smem (half2 units): Qs[128][36], Ks[256][36], V2[128][72] = 92,160 B
// ---------------------------------------------------------------------------
#define QS_OFF 0
#define KS_OFF (128 * 36)
#define V2_OFF (KS_OFF + 256 * 36)
#define ATTN_SMEM_BYTES ((V2_OFF + 128 * 72) * 4)

__global__ void __launch_bounds__(256, 1) attn_tc() {
    extern __shared__ uint32_t smu[];
    uint32_t* Qs = smu + QS_OFF;
    uint32_t* Ks = smu + KS_OFF;
    __half2* V2 = (__half2*)(smu + V2_OFF);

    const int b = blockIdx.x >> 3, h = blockIdx.x & 7;
    const int q0 = blockIdx.y << 7;
    const int t = threadIdx.x, warp = t >> 5, lane = t & 31;
    const int g = lane >> 2, tg = lane & 3;

    const __half* qb = g_qh + (size_t)(b * HW + q0) * CA + h * 64;
    const __half* kb = g_kh + (size_t)b * (KL * CA) + h * 64;
    const __half* vb = g_vh + (size_t)b * (KL * CA) + h * 64;

#pragma unroll
    for (int r = 0; r < 4; r++) {        // Q: 128 rows x 8 xfers
        const int idx = t + 256 * r;
        const int row = idx >> 3, j = idx & 7;
        *(uint4*)&Qs[row * 36 + 4 * j] =
            *(const uint4*)(qb + (size_t)row * CA + 8 * j);
    }
#pragma unroll
    for (int r = 0; r < 8; r++) {        // K: 256 rows x 8 xfers
        const int idx = t + 256 * r;
        const int row = idx >> 3, j = idx & 7;
        *(uint4*)&Ks[row * 36 + 4 * j] =
            *(const uint4*)(kb + (size_t)row * CA + 8 * j);
    }
#pragma unroll
    for (int r = 0; r < 16; r++) {       // V -> half2 key-pairs
        const int idx = t + 256 * r;
        const int kp = idx >> 5, d2 = idx & 31;
        const __half2 a = *(const __half2*)(vb + (size_t)(2 * kp) * CA + 2 * d2);
        const __half2 c = *(const __half2*)(vb + (size_t)(2 * kp + 1) * CA + 2 * d2);
        V2[kp * 72 + 2 * d2] = __halves2half2(__low2half(a), __low2half(c));
        V2[kp * 72 + 2 * d2 + 1] = __halves2half2(__high2half(a), __high2half(c));
    }
    __syncthreads();

    // Q fragments (4 k16-steps over d=64)
    uint32_t qf[4][4];
    const uint32_t* qw = Qs + warp * 16 * 36;
#pragma unroll
    for (int kc = 0; kc < 4; kc++) {
        const int hk = kc * 8 + tg;
        qf[kc][0] = qw[g * 36 + hk];
        qf[kc][1] = qw[(g + 8) * 36 + hk];
        qf[kc][2] = qw[g * 36 + hk + 4];
        qf[kc][3] = qw[(g + 8) * 36 + hk + 4];
    }

    // --- S = Q K^T ---
    float sc[32][4];
#pragma unroll
    for (int j = 0; j < 32; j++)
#pragma unroll
        for (int i = 0; i < 4; i++) sc[j][i] = 0.f;

#pragma unroll
    for (int j = 0; j < 32; j++) {       // key octet j
        const uint32_t* kr = Ks + (j * 8 + g) * 36;
#pragma unroll
        for (int kc = 0; kc < 4; kc++) {
            uint32_t bf[2];
            bf[0] = kr[kc * 8 + tg];
            bf[1] = kr[kc * 8 + tg + 4];
            mma_f16(sc[j], qf[kc], bf);
        }
    }

    // --- softmax (rows g, g+8; scale = 0.125) ---
    uint32_t pl[32], ph[32];
    {
        float m0 = -1e30f, m1 = -1e30f;
#pragma unroll
        for (int j = 0; j < 32; j++) {
            m0 = fmaxf(m0, fmaxf(sc[j][0], sc[j][1]));
            m1 = fmaxf(m1, fmaxf(sc[j][2], sc[j][3]));
        }
        m0 = fmaxf(m0, __shfl_xor_sync(0xffffffffu, m0, 1));
        m0 = fmaxf(m0, __shfl_xor_sync(0xffffffffu, m0, 2));
        m1 = fmaxf(m1, __shfl_xor_sync(0xffffffffu, m1, 1));
        m1 = fmaxf(m1, __shfl_xor_sync(0xffffffffu, m1, 2));
        float s0 = 0.f, s1 = 0.f;
#pragma unroll
        for (int j = 0; j < 32; j++) {
            sc[j][0] = __expf(0.125f * (sc[j][0] - m0));
            sc[j][1] = __expf(0.125f * (sc[j][1] - m0));
            sc[j][2] = __expf(0.125f * (sc[j][2] - m1));
            sc[j][3] = __expf(0.125f * (sc[j][3] - m1));
            s0 += sc[j][0] + sc[j][1];
            s1 += sc[j][2] + sc[j][3];
        }
        s0 += __shfl_xor_sync(0xffffffffu, s0, 1);
        s0 += __shfl_xor_sync(0xffffffffu, s0, 2);
        s1 += __shfl_xor_sync(0xffffffffu, s1, 1);
        s1 += __shfl_xor_sync(0xffffffffu, s1, 2);
        const float i0 = __frcp_rn(s0), i1 = __frcp_rn(s1);
#pragma unroll
        for (int j = 0; j < 32; j++) {
            const __half2 lo = __floats2half2_rn(sc[j][0] * i0, sc[j][1] * i0);
            const __half2 hi = __floats2half2_rn(sc[j][2] * i1, sc[j][3] * i1);
            pl[j] = *(const uint32_t*)&lo;
            ph[j] = *(const uint32_t*)&hi;
        }
    }

    // --- O = P V ---
    float oc[8][4];
#pragma unroll
    for (int ni = 0; ni < 8; ni++)
#pragma unroll
        for (int i = 0; i < 4; i++) oc[ni][i] = 0.f;

#pragma unroll
    for (int kc = 0; kc < 16; kc++) {
        uint32_t a[4];
        a[0] = pl[2 * kc];
        a[1] = ph[2 * kc];
        a[2] = pl[2 * kc + 1];
        a[3] = ph[2 * kc + 1];
        const __half2* vr0 = V2 + (kc * 8 + tg) * 72;
        const __half2* vr1 = V2 + (kc * 8 + tg + 4) * 72;
#pragma unroll
        for (int ni = 0; ni < 8; ni++) {
            uint32_t bf[2];
            bf[0] = *(const uint32_t*)&vr0[ni * 8 + g];
            bf[1] = *(const uint32_t*)&vr1[ni * 8 + g];
            mma_f16(oc[ni], a, bf);
        }
    }

    __half* ob = g_attnh + (size_t)(b * HW + q0 + warp * 16) * CA + h * 64;
#pragma unroll
    for (int ni = 0; ni < 8; ni++) {
        const int col = ni * 8 + 2 * tg;
        *(__half2*)&ob[(size_t)g * CA + col] =
            __floats2half2_rn(oc[ni][0], oc[ni][1]);
        *(__half2*)&ob[(size_t)(g + 8) * CA + col] =
            __floats2half2_rn(oc[ni][2], oc[ni][3]);
    }
}

// ---------------------------------------------------------------------------
// Residual + LayerNorm + transpose to [b, c, h, w].
// ---------------------------------------------------------------------------
#define LN_SMEM_BYTES (32 * 513 * 4)

__global__ void __launch_bounds__(256, 1)
ln_kernel(const float* __restrict__ img, const float* __restrict__ gamma,
          const float* __restrict__ beta, float* __restrict__ out) {
    extern __shared__ float sm[];   // [32][513]
    __shared__ float smu2[32], srv[32];
    const int b = blockIdx.x >> 5;
    const int s0 = (blockIdx.x & 31) << 5;
    const int t = threadIdx.x;

#pragma unroll
    for (int r = 0; r < 16; r++) {
        const int u = t + 256 * r;
        const int s = u >> 7, c4 = (u & 127) << 2;
        const float4 v = *(const float4*)&g_y[((size_t)(b * HW + s0 + s)) * CI + c4];
        float* dst = sm + s * 513 + c4;
        dst[0] = v.x; dst[1] = v.y; dst[2] = v.z; dst[3] = v.w;
    }
    __syncthreads();
#pragma unroll 8
    for (int r = 0; r < 64; r++) {
        const int u = t + 256 * r;
        const int c = u >> 5, s = u & 31;
        sm[s * 513 + c] += img[(size_t)b * (CI * HW) + (size_t)c * HW + s0 + s];
    }
    __syncthreads();

    const int warp = t >> 5, lane = t & 31;
#pragma unroll
    for (int rr = 0; rr < 4; rr++) {
        const int s = warp * 4 + rr;
        const float* row = sm + s * 513;
        float sum = 0.f;
#pragma unroll
        for (int i = 0; i < 16; i++) sum += row[lane + 32 * i];
#pragma unroll
        for (int off = 16; off > 0; off >>= 1)
            sum += __shfl_xor_sync(0xffffffffu, sum, off);
        const float mu = sum * (1.0f / 512.0f);
        float var = 0.f;
#pragma unroll
        for (int i = 0; i < 16; i++) {
            const float d = row[lane + 32 * i] - mu;
            var += d * d;
        }
#pragma unroll
        for (int off = 16; off > 0; off >>= 1)
            var += __shfl_xor_sync(0xffffffffu, var, off);
        var *= (1.0f / 512.0f);
        if (lane == 0) { smu2[s] = mu; srv[s] = rsqrtf(var + 1e-5f); }
    }
    __syncthreads();

    const float mu = smu2[lane], rv = srv[lane];
#pragma unroll 4
    for (int ci = 0; ci < 64; ci++) {
        const int c = warp * 64 + ci;
        const float val = (sm[lane * 513 + c] - mu) * rv * gamma[c] + beta[c];
        out[(size_t)b * (CI * HW) + (size_t)c * HW + s0 + lane] = val;
    }
}

// ---------------------------------------------------------------------------
extern "C" void kernel_launch(void* const* d_in, const int* in_sizes, int n_in,
                              void* d_out, int out_size) {
    (void)in_sizes; (void)n_in; (void)out_size;
    const float* img   = (const float*)d_in[0];
    const float* aud   = (const float*)d_in[1];
    const float* Wq    = (const float*)d_in[2];
    const float* bq    = (const float*)d_in[3];
    const float* Wk    = (const float*)d_in[4];
    const float* bk    = (const float*)d_in[5];
    const float* Wv    = (const float*)d_in[6];
    const float* bv    = (const float*)d_in[7];
    const float* Wo    = (const float*)d_in[8];
    const float* bo    = (const float*)d_in[9];
    const float* gamma = (const float*)d_in[10];
    const float* beta  = (const float*)d_in[11];
    float* out = (float*)d_out;

    cudaFuncSetAttribute((const void*)gemm_h<0>,
                         cudaFuncAttributeMaxDynamicSharedMemorySize, GT_SMEM_BYTES);
    cudaFuncSetAttribute((const void*)gemm_h<1>,
                         cudaFuncAttributeMaxDynamicSharedMemorySize, GT_SMEM_BYTES);
    cudaFuncSetAttribute((const void*)gemm_h<2>,
                         cudaFuncAttributeMaxDynamicSharedMemorySize, GT_SMEM_BYTES);
    cudaFuncSetAttribute((const void*)gemm_h<3>,
                         cudaFuncAttributeMaxDynamicSharedMemorySize, GT_SMEM_BYTES);
    cudaFuncSetAttribute((const void*)attn_tc,
                         cudaFuncAttributeMaxDynamicSharedMemorySize, ATTN_SMEM_BYTES);
    cudaFuncSetAttribute((const void*)ln_kernel,
                         cudaFuncAttributeMaxDynamicSharedMemorySize, LN_SMEM_BYTES);

    // fp16 conversions (replace tf32 rounding; also fold in transposes)
    cvt_img_t<<<dim3(16, 32, 16), dim3(32, 8)>>>(img);
    cvt_aud<<<NB * KL * CA / 4 / 256, 256>>>((const float4*)aud);
    cvt_w_t<<<dim3(16, 16, 4), dim3(32, 8)>>>(Wq, Wk, Wv, Wo);

    gemm_h<0><<<dim3(4, 128), 256, GT_SMEM_BYTES>>>(bq);
    gemm_h<1><<<dim3(4, 32), 256, GT_SMEM_BYTES>>>(bk);
    gemm_h<2><<<dim3(4, 32), 256, GT_SMEM_BYTES>>>(bv);
    attn_tc<<<dim3(128, 8), 256, ATTN_SMEM_BYTES>>>();
    gemm_h<3><<<dim3(4, 128), 256, GT_SMEM_BYTES>>>(bo);
    ln_kernel<<<512, 256, LN_SMEM_BYTES>>>(img, gamma, beta, out);
}